// round 2
// baseline (speedup 1.0000x reference)
#include <cuda_runtime.h>

// Scratch bitmaps (graph-capturable: no allocations, __device__ globals).
// g_bm1: level-1 touched bitmap, (cap/2) bits = 4M bits = 131072 words.
// g_bmu: bitmaps for levels 2..12, laid out back-to-back (131008 words used).
#define BM1_WORDS 131072
__device__ unsigned g_bm1[BM1_WORDS];
__device__ unsigned g_bmu[131072];

// Full tree copy (float4-vectorized) + clear the atomically-built bm1 so every
// graph replay starts from a clean bitmap.
__global__ void __launch_bounds__(256) k_copy(const float4* __restrict__ src,
                                              float4* __restrict__ dst, int n4) {
    int i = blockIdx.x * blockDim.x + threadIdx.x;
    if (i < n4) dst[i] = src[i];
    if (i < BM1_WORDS) g_bm1[i] = 0u;
}

// Scatter leaf values and mark the level-1 parent bitmap.
__global__ void __launch_bounds__(256) k_scatter(const int* __restrict__ idx,
                                                 const float* __restrict__ vals,
                                                 float* __restrict__ tree, int n,
                                                 unsigned cap) {
    int i = blockIdx.x * blockDim.x + threadIdx.x;
    if (i >= n) return;
    unsigned id = (unsigned)idx[i];
    tree[cap + id] = vals[i];
    unsigned p = id >> 1;                      // level-1 node index
    atomicOr(&g_bm1[p >> 5], 1u << (p & 31u));
}

// One thread per node at level L.
//  pair==0 (L==1): touched = own bit in bm1.
//  pair==1 (L>=2): touched = OR of the two child bits in level-(L-1) bitmap.
// Each warp emits the level-L bitmap word via ballot (read by level L+1).
// Touched nodes recompute parent = left + right (deterministic, written once).
__global__ void __launch_bounds__(256) k_level(float* __restrict__ tree, unsigned nodes,
                                               int in_off, int out_off,
                                               int pair, int in_is_bm1) {
    unsigned j = blockIdx.x * blockDim.x + threadIdx.x;
    const unsigned* __restrict__ bin = in_is_bm1 ? g_bm1 : (g_bmu + in_off);
    bool touched = false;
    if (j < nodes) {
        if (pair) touched = (bin[j >> 4] >> ((j & 15u) * 2u)) & 3u;  // bits 2j, 2j+1
        else      touched = (bin[j >> 5] >> (j & 31u)) & 1u;
    }
    unsigned ball = __ballot_sync(0xffffffffu, touched);
    if (out_off >= 0 && (threadIdx.x & 31u) == 0u)
        g_bmu[out_off + (j >> 5)] = ball;
    if (touched) {
        unsigned p = nodes + j;                // tree index (level base == node count)
        float2 c = *(const float2*)(tree + 2ull * (unsigned long long)p);
        tree[p] = c.x + c.y;
    }
}

// Fused top: levels 13..23 (1024 nodes down to the root) in ONE block.
// Touched flags carried level-to-level in shared memory; global tree writes at
// level L are visible to level L+1 readers via __syncthreads (single SM, L1).
__global__ void __launch_bounds__(1024) k_top(float* __restrict__ tree, int bm12_off,
                                              unsigned cap) {
    __shared__ unsigned char flag[1024];
    const unsigned* __restrict__ bm12 = g_bmu + bm12_off;
    unsigned t = threadIdx.x;
    unsigned nodes = cap >> 13;                // 1024
    bool touched = false;
    if (t < nodes) {
        touched = (bm12[t >> 4] >> ((t & 15u) * 2u)) & 3u;
        if (touched) {
            unsigned p = nodes + t;
            float2 c = *(const float2*)(tree + 2ull * (unsigned long long)p);
            tree[p] = c.x + c.y;
        }
    }
    flag[t] = (unsigned char)touched;
    __syncthreads();
    for (nodes >>= 1; nodes >= 1; nodes >>= 1) {
        bool tt = false;
        if (t < nodes) {
            tt = flag[2 * t] | flag[2 * t + 1];
            if (tt) {
                unsigned p = nodes + t;
                float2 c = *(const float2*)(tree + 2ull * (unsigned long long)p);
                tree[p] = c.x + c.y;
            }
        }
        __syncthreads();
        flag[t] = (t < nodes) ? (unsigned char)tt : (unsigned char)0;
        __syncthreads();
    }
}

extern "C" void kernel_launch(void* const* d_in, const int* in_sizes, int n_in,
                              void* d_out, int out_size) {
    // Identify inputs: tree_values matches out_size; remaining two (in metadata
    // order) are indices (int32) then values (float32).
    int ti = 0;
    for (int i = 0; i < n_in; i++) if (in_sizes[i] == out_size) { ti = i; break; }
    int others[2]; int c = 0;
    for (int i = 0; i < n_in && c < 2; i++) if (i != ti) others[c++] = i;

    const float* tree_in = (const float*)d_in[ti];
    const int*   indices = (const int*)d_in[others[0]];
    const float* values  = (const float*)d_in[others[1]];
    float* out = (float*)d_out;

    unsigned total = (unsigned)out_size;       // 2 * capacity = 16,777,216
    unsigned cap   = total >> 1;               // 8,388,608 = 2^23
    int n = in_sizes[others[0]];               // 1,048,576 updates

    // 1) copy whole tree + clear bm1
    int n4 = (int)(total >> 2);
    k_copy<<<(n4 + 255) / 256, 256>>>((const float4*)tree_in, (float4*)out, n4);

    // 2) scatter leaves + build level-1 bitmap
    k_scatter<<<(n + 255) / 256, 256>>>(indices, values, out, n, cap);

    // Bitmap offsets for levels 2..12 inside g_bmu.
    int off[13];
    off[2] = 0;
    for (int L = 3; L <= 12; L++) {
        unsigned prev_nodes = cap >> (L - 1);
        int w = (int)(prev_nodes >> 5); if (w < 1) w = 1;
        off[L] = off[L - 1] + w;
    }

    // 3) level 1: touched directly from bm1 (no ballot output; level 2 reads bm1 pairs)
    {
        unsigned nodes = cap >> 1;
        k_level<<<(nodes + 255) / 256, 256>>>(out, nodes, 0, -1, 0, 1);
    }
    // 4) levels 2..12: pair-read previous bitmap, ballot-write own bitmap
    for (int L = 2; L <= 12; L++) {
        unsigned nodes = cap >> L;
        int in_off    = (L == 2) ? 0 : off[L - 1];
        int in_is_bm1 = (L == 2) ? 1 : 0;
        k_level<<<(nodes + 255) / 256, 256>>>(out, nodes, in_off, off[L], 1, in_is_bm1);
    }
    // 5) levels 13..23 fused in one block
    k_top<<<1, 1024>>>(out, off[12], cap);
}

// round 3
// speedup vs baseline: 1.3578x; 1.3578x over previous
#include <cuda_runtime.h>

// Scratch (graph-capturable: __device__ globals, no allocations).
// g_bm1: level-1 touched bitmap, 4M bits. Cleared each replay by k_copy.
// g_f12: level-12 touched flags (2048), written unconditionally each replay.
#define BM1_WORDS 131072
__device__ unsigned g_bm1[BM1_WORDS];
__device__ unsigned char g_f12[2048];

// Full tree copy (float4) + clear bm1 for this replay.
__global__ void __launch_bounds__(256) k_copy(const float4* __restrict__ src,
                                              float4* __restrict__ dst, int n4) {
    int i = blockIdx.x * blockDim.x + threadIdx.x;
    if (i < n4) dst[i] = src[i];
    if (i < BM1_WORDS) g_bm1[i] = 0u;
}

// Scatter leaf values; mark level-1 parent bitmap.
__global__ void __launch_bounds__(256) k_scatter(const int* __restrict__ idx,
                                                 const float* __restrict__ vals,
                                                 float* __restrict__ tree, int n,
                                                 unsigned cap) {
    int i = blockIdx.x * blockDim.x + threadIdx.x;
    if (i >= n) return;
    unsigned id = (unsigned)idx[i];
    tree[cap + id] = vals[i];
    unsigned p = id >> 1;
    atomicOr(&g_bm1[p >> 5], 1u << (p & 31u));
}

// Fused propagation, levels 1..12. Each block owns 2048 level-1 nodes (a full
// subtree down to one level-12 node). Child values for levels >=2 come from
// shared-memory ping-pong buffers; untouched nodes take their original global
// value (== their new value, so stores can be unconditional & coalesced).
#define CHUNK 2048
#define PTHREADS 512

__global__ void __launch_bounds__(PTHREADS) k_prop(float* __restrict__ tree,
                                                   unsigned cap) {
    __shared__ float vA[CHUNK];
    __shared__ float vB[CHUNK / 2];
    __shared__ unsigned char fA[CHUNK];
    __shared__ unsigned char fB[CHUNK / 2];
    unsigned b = blockIdx.x, t = threadIdx.x;
    unsigned lvl1 = cap >> 1;                 // 4M level-1 nodes
    unsigned base = b * CHUNK;

    // Level 1: 4 consecutive nodes per thread, fully vectorized.
    {
        unsigned j = base + t * 4u;           // level-1 node index (4-aligned)
        unsigned word = g_bm1[j >> 5];
        unsigned sh = j & 31u;
        unsigned p = lvl1 + j;                // tree index
        float4 orig = *(const float4*)(tree + p);
        float4 c0 = *(const float4*)(tree + 2u * p);       // children j..j+1
        float4 c1 = *(const float4*)(tree + 2u * p + 4u);  // children j+2..j+3
        bool t0 = (word >> (sh + 0)) & 1u, t1 = (word >> (sh + 1)) & 1u,
             t2 = (word >> (sh + 2)) & 1u, t3 = (word >> (sh + 3)) & 1u;
        float4 v;
        v.x = t0 ? c0.x + c0.y : orig.x;
        v.y = t1 ? c0.z + c0.w : orig.y;
        v.z = t2 ? c1.x + c1.y : orig.z;
        v.w = t3 ? c1.z + c1.w : orig.w;
        *(float4*)(tree + p) = v;             // unconditional, coalesced
        unsigned k = t * 4u;
        vA[k] = v.x; vA[k + 1] = v.y; vA[k + 2] = v.z; vA[k + 3] = v.w;
        fA[k] = t0;  fA[k + 1] = t1;  fA[k + 2] = t2;  fA[k + 3] = t3;
    }
    __syncthreads();

    // Levels 2..12 (node counts 1024 .. 1), children from smem.
    float* vin = vA;  float* vout = vB;
    unsigned char* fin = fA; unsigned char* fout = fB;
    unsigned n = CHUNK >> 1;
    for (int L = 2; L <= 12; L++, n >>= 1) {
        for (unsigned j = t; j < n; j += PTHREADS) {
            unsigned gj = b * n + j;          // global node index at level L
            unsigned p = (cap >> L) + gj;     // tree index
            bool tt = fin[2 * j] | fin[2 * j + 1];
            float v = tt ? vin[2 * j] + vin[2 * j + 1] : tree[p];
            tree[p] = v;
            vout[j] = v; fout[j] = (unsigned char)tt;
        }
        __syncthreads();
        float* tv = vin; vin = vout; vout = tv;
        unsigned char* tf = fin; fin = fout; fout = tf;
    }
    if (t == 0) g_f12[b] = fin[0];            // this subtree's level-12 flag
}

// Fused top: levels 13..23 in one block of 1024 threads.
__global__ void __launch_bounds__(1024) k_top(float* __restrict__ tree) {
    __shared__ float val[1024];
    __shared__ unsigned char fl[1024];
    unsigned t = threadIdx.x;
    // Level 13: 1024 nodes; children are the level-12 values written by k_prop.
    bool tt = g_f12[2 * t] | g_f12[2 * t + 1];
    unsigned p = 1024u + t;
    float v = tt ? tree[2 * p] + tree[2 * p + 1] : tree[p];
    tree[p] = v;
    val[t] = v; fl[t] = (unsigned char)tt;
    __syncthreads();
    for (unsigned n = 512; n >= 1; n >>= 1) {
        bool t2 = false; float v2 = 0.0f;
        if (t < n) {
            t2 = fl[2 * t] | fl[2 * t + 1];
            unsigned pp = n + t;
            v2 = t2 ? val[2 * t] + val[2 * t + 1] : tree[pp];
            tree[pp] = v2;
        }
        __syncthreads();
        if (t < n) { val[t] = v2; fl[t] = (unsigned char)t2; }
        __syncthreads();
    }
}

extern "C" void kernel_launch(void* const* d_in, const int* in_sizes, int n_in,
                              void* d_out, int out_size) {
    // tree_values matches out_size; remaining two (metadata order) are
    // indices (int32) then values (float32).
    int ti = 0;
    for (int i = 0; i < n_in; i++) if (in_sizes[i] == out_size) { ti = i; break; }
    int others[2]; int c = 0;
    for (int i = 0; i < n_in && c < 2; i++) if (i != ti) others[c++] = i;

    const float* tree_in = (const float*)d_in[ti];
    const int*   indices = (const int*)d_in[others[0]];
    const float* values  = (const float*)d_in[others[1]];
    float* out = (float*)d_out;

    unsigned total = (unsigned)out_size;      // 16,777,216
    unsigned cap   = total >> 1;              // 8,388,608 = 2^23
    int n = in_sizes[others[0]];              // 1,048,576

    int n4 = (int)(total >> 2);
    k_copy<<<(n4 + 255) / 256, 256>>>((const float4*)tree_in, (float4*)out, n4);
    k_scatter<<<(n + 255) / 256, 256>>>(indices, values, out, n, cap);

    unsigned nblocks = (cap >> 1) / CHUNK;    // 2048
    k_prop<<<nblocks, PTHREADS>>>(out, cap);
    k_top<<<1, 1024>>>(out);
}

// round 5
// speedup vs baseline: 1.4462x; 1.0651x over previous
#include <cuda_runtime.h>

// Scratch (graph-capturable: __device__ globals, no allocations).
#define BM1_WORDS 131072
__device__ unsigned g_bm1[BM1_WORDS];        // level-1 touched bitmap (4M bits)
__device__ unsigned char g_f12[2048];        // level-12 touched flags
__device__ unsigned g_done;                  // last-block counter

// Copy ONLY the leaves [cap, 2cap) + tree[0]; every other node is written
// unconditionally by k_prop (levels 1-12) or the fused top (levels 13-23),
// which read untouched originals straight from src. Also clears bm1/counter.
__global__ void __launch_bounds__(256) k_copy(const float4* __restrict__ src,
                                              float4* __restrict__ dst,
                                              int leaf4_off, int n4) {
    int i = blockIdx.x * blockDim.x + threadIdx.x;
    if (i < n4) dst[leaf4_off + i] = src[leaf4_off + i];
    if (i < BM1_WORDS) g_bm1[i] = 0u;
    if (i == 0) {
        g_done = 0u;
        ((float*)dst)[0] = ((const float*)src)[0];
    }
}

// Scatter leaf values; mark level-1 parent bitmap.
__global__ void __launch_bounds__(256) k_scatter(const int* __restrict__ idx,
                                                 const float* __restrict__ vals,
                                                 float* __restrict__ tree, int n,
                                                 unsigned cap) {
    int i = blockIdx.x * blockDim.x + threadIdx.x;
    if (i >= n) return;
    unsigned id = (unsigned)idx[i];
    tree[cap + id] = vals[i];
    unsigned p = id >> 1;
    atomicOr(&g_bm1[p >> 5], 1u << (p & 31u));
}

// Fused propagation, levels 1..23. Each block owns 2048 level-1 nodes (a full
// subtree down to one level-12 node); the LAST block to finish also runs
// levels 13..23 (canonical threadFenceReduction pattern). Children for levels
// >=2 come from shared-memory ping-pong; untouched nodes read their original
// value from src (never from dst).
#define CHUNK 2048
#define PTHREADS 512

__global__ void __launch_bounds__(PTHREADS) k_prop(float* __restrict__ dst,
                                                   const float* __restrict__ src,
                                                   unsigned cap) {
    __shared__ float vA[CHUNK];
    __shared__ float vB[CHUNK / 2];
    __shared__ unsigned char fA[CHUNK];
    __shared__ unsigned char fB[CHUNK / 2];
    __shared__ unsigned s_islast;
    unsigned b = blockIdx.x, t = threadIdx.x;
    unsigned lvl1 = cap >> 1;                 // 4M level-1 nodes
    unsigned base = b * CHUNK;

    // Level 1: 4 consecutive nodes per thread, fully vectorized.
    {
        unsigned j = base + t * 4u;           // level-1 node index (4-aligned)
        unsigned word = g_bm1[j >> 5];
        unsigned sh = j & 31u;
        unsigned p = lvl1 + j;                // tree index
        float4 orig = *(const float4*)(src + p);
        float4 c0 = *(const float4*)(dst + 2u * p);        // children j..j+1
        float4 c1 = *(const float4*)(dst + 2u * p + 4u);   // children j+2..j+3
        bool t0 = (word >> (sh + 0)) & 1u, t1 = (word >> (sh + 1)) & 1u,
             t2 = (word >> (sh + 2)) & 1u, t3 = (word >> (sh + 3)) & 1u;
        float4 v;
        v.x = t0 ? c0.x + c0.y : orig.x;
        v.y = t1 ? c0.z + c0.w : orig.y;
        v.z = t2 ? c1.x + c1.y : orig.z;
        v.w = t3 ? c1.z + c1.w : orig.w;
        *(float4*)(dst + p) = v;              // unconditional, coalesced
        unsigned k = t * 4u;
        vA[k] = v.x; vA[k + 1] = v.y; vA[k + 2] = v.z; vA[k + 3] = v.w;
        fA[k] = t0;  fA[k + 1] = t1;  fA[k + 2] = t2;  fA[k + 3] = t3;
    }
    __syncthreads();

    // Levels 2..12 (node counts 1024 .. 1 per block), children from smem.
    float* vin = vA;  float* vout = vB;
    unsigned char* fin = fA; unsigned char* fout = fB;
    unsigned n = CHUNK >> 1;
    for (int L = 2; L <= 12; L++, n >>= 1) {
        for (unsigned j = t; j < n; j += PTHREADS) {
            unsigned gj = b * n + j;          // global node index at level L
            unsigned p = (cap >> L) + gj;     // tree index
            bool tt = fin[2 * j] | fin[2 * j + 1];
            float v = tt ? vin[2 * j] + vin[2 * j + 1] : src[p];
            dst[p] = v;
            vout[j] = v; fout[j] = (unsigned char)tt;
        }
        __syncthreads();
        float* tv = vin; vin = vout; vout = tv;
        unsigned char* tf = fin; fin = fout; fout = tf;
    }
    if (t == 0) g_f12[b] = fin[0];            // this subtree's level-12 flag

    // ---- last-block-done: the final block runs levels 13..23 ----
    __threadfence();                          // publish dst level-12 + g_f12
    __syncthreads();
    if (t == 0) {
        unsigned x = atomicAdd(&g_done, 1u);
        s_islast = (x == gridDim.x - 1u);
    }
    __syncthreads();
    if (!s_islast) return;
    __threadfence();                          // acquire other blocks' writes

    // Level 13: 1024 nodes, children = level-12 values in dst.
    for (unsigned j = t; j < 1024u; j += PTHREADS) {
        bool tt = g_f12[2 * j] | g_f12[2 * j + 1];
        unsigned p = 1024u + j;
        float v = tt ? dst[2 * p] + dst[2 * p + 1] : src[p];
        dst[p] = v;
        vA[j] = v; fA[j] = (unsigned char)tt;
    }
    __syncthreads();
    // Levels 14..23 (512 nodes down to the root), all in smem.
    for (unsigned m = 512; m >= 1; m >>= 1) {
        bool tt = false; float v = 0.0f;
        if (t < m) {
            tt = fA[2 * t] | fA[2 * t + 1];
            unsigned pp = m + t;
            v = tt ? vA[2 * t] + vA[2 * t + 1] : src[pp];
            dst[pp] = v;
        }
        __syncthreads();
        if (t < m) { vA[t] = v; fA[t] = (unsigned char)tt; }
        __syncthreads();
    }
}

extern "C" void kernel_launch(void* const* d_in, const int* in_sizes, int n_in,
                              void* d_out, int out_size) {
    // tree_values matches out_size; remaining two (metadata order) are
    // indices (int32) then values (float32).
    int ti = 0;
    for (int i = 0; i < n_in; i++) if (in_sizes[i] == out_size) { ti = i; break; }
    int others[2]; int c = 0;
    for (int i = 0; i < n_in && c < 2; i++) if (i != ti) others[c++] = i;

    const float* tree_in = (const float*)d_in[ti];
    const int*   indices = (const int*)d_in[others[0]];
    const float* values  = (const float*)d_in[others[1]];
    float* out = (float*)d_out;

    unsigned total = (unsigned)out_size;      // 16,777,216
    unsigned cap   = total >> 1;              // 8,388,608 = 2^23
    int n = in_sizes[others[0]];              // 1,048,576

    int leaf4_off = (int)(cap >> 2);          // leaves start, in float4 units
    int n4 = (int)(cap >> 2);                 // number of leaf float4s
    k_copy<<<(n4 + 255) / 256, 256>>>((const float4*)tree_in, (float4*)out,
                                      leaf4_off, n4);
    k_scatter<<<(n + 255) / 256, 256>>>(indices, values, out, n, cap);

    unsigned nblocks = (cap >> 1) / CHUNK;    // 2048
    k_prop<<<nblocks, PTHREADS>>>(out, tree_in, cap);
}

// round 6
// speedup vs baseline: 1.4932x; 1.0325x over previous
#include <cuda_runtime.h>

// Scratch (graph-capturable: __device__ globals, zero at module load).
// g_bmL: per-LEAF touched bitmap, 8M bits = 262144 words (1 MB).
//        Built by k_scatter (atomicOr); self-cleared by each k_prop block
//        after use, so every run starts clean (deterministic across replays).
#define BML_WORDS 262144
__device__ unsigned g_bmL[BML_WORDS];
__device__ unsigned char g_f12[2048];        // level-12 touched flags
__device__ unsigned g_done;                  // last-block counter (self-reset)

// Scatter leaf values into dst; mark per-leaf bitmap.
__global__ void __launch_bounds__(256) k_scatter(const int* __restrict__ idx,
                                                 const float* __restrict__ vals,
                                                 float* __restrict__ dst, int n,
                                                 unsigned cap) {
    int i = blockIdx.x * blockDim.x + threadIdx.x;
    if (i >= n) return;
    unsigned id = (unsigned)idx[i];
    dst[cap + id] = vals[i];
    atomicOr(&g_bmL[id >> 5], 1u << (id & 31u));
}

// Fused: leaf merge + propagation levels 1..23. Each block owns 2048 level-1
// nodes (4096 leaves; a full subtree down to one level-12 node). Leaves are
// merged from src (untouched) and dst (touched, written by k_scatter) and
// written back to dst coalesced. The LAST block also runs levels 13..23
// (threadFenceReduction pattern). Children for levels >=2 live in smem.
#define CHUNK 2048
#define PTHREADS 512

__global__ void __launch_bounds__(PTHREADS) k_prop(float* __restrict__ dst,
                                                   const float* __restrict__ src,
                                                   unsigned cap) {
    __shared__ float vA[CHUNK];
    __shared__ float vB[CHUNK / 2];
    __shared__ unsigned char fA[CHUNK];
    __shared__ unsigned char fB[CHUNK / 2];
    __shared__ unsigned s_islast;
    unsigned b = blockIdx.x, t = threadIdx.x;
    unsigned lvl1 = cap >> 1;                 // 4M level-1 nodes
    unsigned base = b * CHUNK;

    // Level 0+1: merge 8 leaves, write them, compute 4 level-1 nodes.
    {
        unsigned j = base + t * 4u;           // first level-1 node (4-aligned)
        unsigned leaf = 2u * j;               // first leaf (8-aligned)
        unsigned bits = (g_bmL[leaf >> 5] >> (leaf & 31u)) & 0xFFu;
        unsigned p = lvl1 + j;                // level-1 tree index
        const float4* s4 = (const float4*)(src + cap) + (leaf >> 2);
        float4*       d4 = (float4*)(dst + cap) + (leaf >> 2);
        float4 s0 = s4[0], s1 = s4[1];
        float4 d0, d1;
        if (bits & 0x0Fu) d0 = d4[0];         // touched values live in dst
        if (bits & 0xF0u) d1 = d4[1];
        float4 m0, m1;                        // merged leaves
        m0.x = (bits & 1u)   ? d0.x : s0.x;
        m0.y = (bits & 2u)   ? d0.y : s0.y;
        m0.z = (bits & 4u)   ? d0.z : s0.z;
        m0.w = (bits & 8u)   ? d0.w : s0.w;
        m1.x = (bits & 16u)  ? d1.x : s1.x;
        m1.y = (bits & 32u)  ? d1.y : s1.y;
        m1.z = (bits & 64u)  ? d1.z : s1.z;
        m1.w = (bits & 128u) ? d1.w : s1.w;
        d4[0] = m0; d4[1] = m1;               // unconditional, coalesced
        bool t0 = bits & 0x03u, t1 = bits & 0x0Cu,
             t2 = bits & 0x30u, t3 = bits & 0xC0u;
        float4 orig = *(const float4*)(src + p);
        float4 v;
        v.x = t0 ? m0.x + m0.y : orig.x;
        v.y = t1 ? m0.z + m0.w : orig.y;
        v.z = t2 ? m1.x + m1.y : orig.z;
        v.w = t3 ? m1.z + m1.w : orig.w;
        *(float4*)(dst + p) = v;              // unconditional, coalesced
        unsigned k = t * 4u;
        vA[k] = v.x; vA[k + 1] = v.y; vA[k + 2] = v.z; vA[k + 3] = v.w;
        fA[k] = t0;  fA[k + 1] = t1;  fA[k + 2] = t2;  fA[k + 3] = t3;
    }
    __syncthreads();

    // Self-clear this block's 128 bitmap words for the next replay.
    if (t < 128u) g_bmL[b * 128u + t] = 0u;

    // Levels 2..12 (node counts 1024 .. 1 per block), children from smem.
    float* vin = vA;  float* vout = vB;
    unsigned char* fin = fA; unsigned char* fout = fB;
    unsigned n = CHUNK >> 1;
    for (int L = 2; L <= 12; L++, n >>= 1) {
        for (unsigned j = t; j < n; j += PTHREADS) {
            unsigned gj = b * n + j;          // global node index at level L
            unsigned p = (cap >> L) + gj;     // tree index
            bool tt = fin[2 * j] | fin[2 * j + 1];
            float v = tt ? vin[2 * j] + vin[2 * j + 1] : src[p];
            dst[p] = v;
            vout[j] = v; fout[j] = (unsigned char)tt;
        }
        __syncthreads();
        float* tv = vin; vin = vout; vout = tv;
        unsigned char* tf = fin; fin = fout; fout = tf;
    }
    if (t == 0) g_f12[b] = fin[0];            // this subtree's level-12 flag

    // ---- last-block-done: the final block runs levels 13..23 ----
    __threadfence();                          // publish dst level-12 + g_f12
    __syncthreads();
    if (t == 0) {
        unsigned x = atomicAdd(&g_done, 1u);
        s_islast = (x == gridDim.x - 1u);
    }
    __syncthreads();
    if (!s_islast) return;
    __threadfence();                          // acquire other blocks' writes

    // Level 13: 1024 nodes, children = level-12 values in dst.
    for (unsigned j = t; j < 1024u; j += PTHREADS) {
        bool tt = g_f12[2 * j] | g_f12[2 * j + 1];
        unsigned p = 1024u + j;
        float v = tt ? dst[2 * p] + dst[2 * p + 1] : src[p];
        dst[p] = v;
        vA[j] = v; fA[j] = (unsigned char)tt;
    }
    __syncthreads();
    // Levels 14..23 (512 nodes down to the root), all in smem.
    for (unsigned m = 512; m >= 1; m >>= 1) {
        bool tt = false; float v = 0.0f;
        if (t < m) {
            tt = fA[2 * t] | fA[2 * t + 1];
            unsigned pp = m + t;
            v = tt ? vA[2 * t] + vA[2 * t + 1] : src[pp];
            dst[pp] = v;
        }
        __syncthreads();
        if (t < m) { vA[t] = v; fA[t] = (unsigned char)tt; }
        __syncthreads();
    }
    if (t == 0) {
        dst[0] = src[0];                      // untouched slot 0
        g_done = 0u;                          // reset for next replay
    }
}

extern "C" void kernel_launch(void* const* d_in, const int* in_sizes, int n_in,
                              void* d_out, int out_size) {
    // tree_values matches out_size; remaining two (metadata order) are
    // indices (int32) then values (float32).
    int ti = 0;
    for (int i = 0; i < n_in; i++) if (in_sizes[i] == out_size) { ti = i; break; }
    int others[2]; int c = 0;
    for (int i = 0; i < n_in && c < 2; i++) if (i != ti) others[c++] = i;

    const float* tree_in = (const float*)d_in[ti];
    const int*   indices = (const int*)d_in[others[0]];
    const float* values  = (const float*)d_in[others[1]];
    float* out = (float*)d_out;

    unsigned total = (unsigned)out_size;      // 16,777,216
    unsigned cap   = total >> 1;              // 8,388,608 = 2^23
    int n = in_sizes[others[0]];              // 1,048,576

    k_scatter<<<(n + 255) / 256, 256>>>(indices, values, out, n, cap);
    unsigned nblocks = (cap >> 1) / CHUNK;    // 2048
    k_prop<<<nblocks, PTHREADS>>>(out, tree_in, cap);
}

// round 7
// speedup vs baseline: 2.0139x; 1.3487x over previous
#include <cuda_runtime.h>

// Scratch (graph-capturable: __device__ globals, zero at module load).
// g_bmL: per-LEAF touched bitmap, 8M bits = 262144 words. Built by k_scatter
//        (atomicOr); self-cleared by each k_prop block after use.
#define BML_WORDS 262144
__device__ unsigned g_bmL[BML_WORDS];
__device__ unsigned char g_f13[1024];        // level-13 touched flags
__device__ unsigned g_done;                  // last-block counter (self-reset)

// Scatter leaf values into dst; mark per-leaf bitmap.
__global__ void __launch_bounds__(256) k_scatter(const int* __restrict__ idx,
                                                 const float* __restrict__ vals,
                                                 float* __restrict__ dst, int n,
                                                 unsigned cap) {
    int i = blockIdx.x * blockDim.x + threadIdx.x;
    if (i >= n) return;
    unsigned id = (unsigned)idx[i];
    dst[cap + id] = vals[i];
    atomicOr(&g_bmL[id >> 5], 1u << (id & 31u));
}

// Fused: leaf merge + propagation levels 1..23. Each block owns 4096 level-1
// nodes (8192 leaves; a full subtree up to one level-13 node). All level-1
// loads are UNCONDITIONAL (dst leaf lines are L2-dirty from scatter), so the
// bitmap load gates only selects, never loads. The LAST block runs levels
// 14..23 (threadFenceReduction pattern).
#define CHUNK 4096
#define PTHREADS 512

__global__ void __launch_bounds__(PTHREADS) k_prop(float* __restrict__ dst,
                                                   const float* __restrict__ src,
                                                   unsigned cap) {
    __shared__ __align__(16) float vA[CHUNK];
    __shared__ __align__(16) float vB[CHUNK / 2];
    __shared__ __align__(16) unsigned char fA[CHUNK];
    __shared__ __align__(16) unsigned char fB[CHUNK / 2];
    __shared__ unsigned s_islast;
    unsigned b = blockIdx.x, t = threadIdx.x;
    unsigned lvl1 = cap >> 1;                 // 4M level-1 nodes
    unsigned base = b * CHUNK;

    // Level 0+1: two independent 4-node groups per thread (8 nodes, 16 leaves).
    #pragma unroll
    for (unsigned g = 0; g < 2; g++) {
        unsigned j = base + (t + g * PTHREADS) * 4u;   // level-1 node (4-aligned)
        unsigned leaf = 2u * j;                        // leaf (8-aligned)
        unsigned bits = (g_bmL[leaf >> 5] >> (leaf & 31u)) & 0xFFu;
        unsigned p = lvl1 + j;
        const float4* s4 = (const float4*)(src + cap) + (leaf >> 2);
        float4*       d4 = (float4*)(dst + cap) + (leaf >> 2);
        float4 s0 = __ldcs(&s4[0]), s1 = __ldcs(&s4[1]);
        float4 d0 = d4[0], d1 = d4[1];                 // unconditional (L2 dirty)
        float4 orig = __ldcs((const float4*)(src + p));
        float4 m0, m1;                                 // merged leaves
        m0.x = (bits & 1u)   ? d0.x : s0.x;
        m0.y = (bits & 2u)   ? d0.y : s0.y;
        m0.z = (bits & 4u)   ? d0.z : s0.z;
        m0.w = (bits & 8u)   ? d0.w : s0.w;
        m1.x = (bits & 16u)  ? d1.x : s1.x;
        m1.y = (bits & 32u)  ? d1.y : s1.y;
        m1.z = (bits & 64u)  ? d1.z : s1.z;
        m1.w = (bits & 128u) ? d1.w : s1.w;
        __stcs(&d4[0], m0); __stcs(&d4[1], m1);        // streaming, coalesced
        bool t0 = bits & 0x03u, t1 = bits & 0x0Cu,
             t2 = bits & 0x30u, t3 = bits & 0xC0u;
        float4 v;
        v.x = t0 ? m0.x + m0.y : orig.x;
        v.y = t1 ? m0.z + m0.w : orig.y;
        v.z = t2 ? m1.x + m1.y : orig.z;
        v.w = t3 ? m1.z + m1.w : orig.w;
        __stcs((float4*)(dst + p), v);                 // final, never re-read
        unsigned k = (t + g * PTHREADS) * 4u - g * PTHREADS * 4u + g * PTHREADS * 4u;
        k = (t + g * PTHREADS) * 4u - base + base - base; // (simplify below)
        k = (t + g * PTHREADS) * 4u;                   // local index in [0, CHUNK)
        vA[k] = v.x; vA[k + 1] = v.y; vA[k + 2] = v.z; vA[k + 3] = v.w;
        fA[k] = t0;  fA[k + 1] = t1;  fA[k + 2] = t2;  fA[k + 3] = t3;
    }
    __syncthreads();

    // Self-clear this block's 256 bitmap words for the next replay.
    if (t < 256u) g_bmL[b * 256u + t] = 0u;

    // Level 2: n=2048, 4 nodes/thread, fully vectorized, unconditional src.
    {
        unsigned j0 = 4u * t;                          // local node index
        float4 c0 = *(const float4*)(vA + 2u * j0);
        float4 c1 = *(const float4*)(vA + 2u * j0 + 4u);
        unsigned w0 = *(const unsigned*)(fA + 2u * j0);
        unsigned w1 = *(const unsigned*)(fA + 2u * j0 + 4u);
        unsigned p = (cap >> 2) + b * 2048u + j0;
        float4 s = __ldcs((const float4*)(src + p));
        bool t0 = (w0 & 0x0000FFFFu) != 0u, t1 = (w0 & 0xFFFF0000u) != 0u,
             t2 = (w1 & 0x0000FFFFu) != 0u, t3 = (w1 & 0xFFFF0000u) != 0u;
        float4 v;
        v.x = t0 ? c0.x + c0.y : s.x;
        v.y = t1 ? c0.z + c0.w : s.y;
        v.z = t2 ? c1.x + c1.y : s.z;
        v.w = t3 ? c1.z + c1.w : s.w;
        *(float4*)(dst + p) = v;
        *(float4*)(vB + j0) = v;
        uchar4 f; f.x = t0; f.y = t1; f.z = t2; f.w = t3;
        *(uchar4*)(fB + j0) = f;
    }
    __syncthreads();

    // Level 3: n=1024, 2 nodes/thread.
    {
        unsigned j0 = 2u * t;
        float4 c = *(const float4*)(vB + 2u * j0);
        unsigned w = *(const unsigned*)(fB + 2u * j0);
        unsigned p = (cap >> 3) + b * 1024u + j0;
        float2 s = __ldcs((const float2*)(src + p));
        bool t0 = (w & 0x0000FFFFu) != 0u, t1 = (w & 0xFFFF0000u) != 0u;
        float2 v;
        v.x = t0 ? c.x + c.y : s.x;
        v.y = t1 ? c.z + c.w : s.y;
        *(float2*)(dst + p) = v;
        vA[j0] = v.x; vA[j0 + 1] = v.y;
        fA[j0] = t0;  fA[j0 + 1] = t1;
    }
    __syncthreads();

    // Levels 4..13 (node counts 512 .. 1 per block), scalar, children in smem.
    float* vin = vA;  float* vout = vB;
    unsigned char* fin = fA; unsigned char* fout = fB;
    unsigned n = 512;
    for (int L = 4; L <= 13; L++, n >>= 1) {
        if (t < n) {
            unsigned j = t;
            unsigned p = (cap >> L) + b * n + j;
            bool tt = fin[2 * j] | fin[2 * j + 1];
            float v = tt ? vin[2 * j] + vin[2 * j + 1] : src[p];
            dst[p] = v;
            vout[j] = v; fout[j] = (unsigned char)tt;
        }
        __syncthreads();
        float* tv = vin; vin = vout; vout = tv;
        unsigned char* tf = fin; fin = fout; fout = tf;
    }
    if (t == 0) g_f13[b] = fin[0];            // this subtree's level-13 flag

    // ---- last-block-done: the final block runs levels 14..23 ----
    __threadfence();                          // publish dst level-13 + g_f13
    __syncthreads();
    if (t == 0) {
        unsigned x = atomicAdd(&g_done, 1u);
        s_islast = (x == gridDim.x - 1u);
    }
    __syncthreads();
    if (!s_islast) return;
    __threadfence();                          // acquire other blocks' writes

    // Level 14: 512 nodes, children = level-13 values in dst (indices 1024+).
    if (t < 512u) {
        bool tt = g_f13[2 * t] | g_f13[2 * t + 1];
        unsigned p = 512u + t;
        float v = tt ? dst[2 * p] + dst[2 * p + 1] : src[p];
        dst[p] = v;
        vA[t] = v; fA[t] = (unsigned char)tt;
    }
    __syncthreads();
    // Levels 15..23 (256 nodes down to the root), all in smem.
    for (unsigned m = 256; m >= 1; m >>= 1) {
        bool tt = false; float v = 0.0f;
        if (t < m) {
            tt = fA[2 * t] | fA[2 * t + 1];
            unsigned pp = m + t;
            v = tt ? vA[2 * t] + vA[2 * t + 1] : src[pp];
            dst[pp] = v;
        }
        __syncthreads();
        if (t < m) { vA[t] = v; fA[t] = (unsigned char)tt; }
        __syncthreads();
    }
    if (t == 0) {
        dst[0] = src[0];                      // untouched slot 0
        g_done = 0u;                          // reset for next replay
    }
}

extern "C" void kernel_launch(void* const* d_in, const int* in_sizes, int n_in,
                              void* d_out, int out_size) {
    // tree_values matches out_size; remaining two (metadata order) are
    // indices (int32) then values (float32).
    int ti = 0;
    for (int i = 0; i < n_in; i++) if (in_sizes[i] == out_size) { ti = i; break; }
    int others[2]; int c = 0;
    for (int i = 0; i < n_in && c < 2; i++) if (i != ti) others[c++] = i;

    const float* tree_in = (const float*)d_in[ti];
    const int*   indices = (const int*)d_in[others[0]];
    const float* values  = (const float*)d_in[others[1]];
    float* out = (float*)d_out;

    unsigned total = (unsigned)out_size;      // 16,777,216
    unsigned cap   = total >> 1;              // 8,388,608 = 2^23
    int n = in_sizes[others[0]];              // 1,048,576

    k_scatter<<<(n + 255) / 256, 256>>>(indices, values, out, n, cap);
    unsigned nblocks = (cap >> 1) / CHUNK;    // 1024
    k_prop<<<nblocks, PTHREADS>>>(out, tree_in, cap);
}